// round 16
// baseline (speedup 1.0000x reference)
#include <cuda_runtime.h>
#include <cuda_fp16.h>

#define BB 128  // batch
#define BU 32   // batch in uint2 units

// ---------------- padded geometry, fp16 (halos stay zero: never written) ---
__device__ __align__(16) __half g_bin[9 * 34 * 34 * BB];
__device__ __align__(16) __half g_h1[32 * 18 * 18 * BB];
__device__ __align__(16) __half g_h2[128 * 10 * 10 * BB];
__device__ __align__(16) __half g_h3[512 * 6 * 6 * BB];
__device__ __align__(16) __half g_h4[4096 * BB];
__device__ __align__(16) __half2 g_mixh[83552 * 4];
__device__ __align__(16) int g_rec[10240 * 16];
__device__ __align__(16) float g_part[640 * BB];

__constant__ float GC[64] = {
    0, 0, 0, 0,   0, 0, 0, 1,   0, 1, 0, -1,  0, 1, 0, 0,
    0, 0, 1, -1,  0, 0, 1, 0,   0, 1, 1, -2,  0, 1, 1, -1,
    1, -1, -1, 1, 1, -1, -1, 2, 1, 0, -1, 0,  1, 0, -1, 1,
    1, -1, 0, 0,  1, -1, 0, 1,  1, 0, 0, -1,  1, 0, 0, 0};

#define OFF_C1 0
#define OFF_C2 224
#define OFF_C3 1120
#define OFF_C4 4704
#define OFF_L1 11872
#define OFF_L2 52832
#define OFF_L3 73312
#define N_NODES 83552
#define MIX_BLOCKS 653   // ceil(83552/128)

// ---------------- helpers ----------------
__device__ __forceinline__ __half2 u2h(unsigned int u) {
    __half2 h;
    *reinterpret_cast<unsigned int*>(&h) = u;
    return h;
}
__device__ __forceinline__ unsigned int h2u(__half2 h) {
    return *reinterpret_cast<unsigned int*>(&h);
}
__device__ __forceinline__ __half2 gateh(__half2 a, __half2 b,
                                         __half2 w0, __half2 w1, __half2 w2, __half2 w3) {
    return __hfma2(__hmul2(a, b), w3, __hfma2(b, w2, __hfma2(a, w1, w0)));
}
__device__ __forceinline__ uint4 gate4u(uint4 a, uint4 b, uint4 cf) {
    __half2 w0 = u2h(cf.x), w1 = u2h(cf.y), w2 = u2h(cf.z), w3 = u2h(cf.w);
    uint4 r;
    r.x = h2u(gateh(u2h(a.x), u2h(b.x), w0, w1, w2, w3));
    r.y = h2u(gateh(u2h(a.y), u2h(b.y), w0, w1, w2, w3));
    r.z = h2u(gateh(u2h(a.z), u2h(b.z), w0, w1, w2, w3));
    r.w = h2u(gateh(u2h(a.w), u2h(b.w), w0, w1, w2, w3));
    return r;
}
__device__ __forceinline__ uint4 max4u(uint4 a, uint4 b) {
    uint4 r;
    r.x = h2u(__hmax2(u2h(a.x), u2h(b.x)));
    r.y = h2u(__hmax2(u2h(a.y), u2h(b.y)));
    r.z = h2u(__hmax2(u2h(a.z), u2h(b.z)));
    r.w = h2u(__hmax2(u2h(a.w), u2h(b.w)));
    return r;
}

// ---------------- kernel 1: gate mixing + logic-chain prep (merged) --------
__global__ void mix_prep_kernel(const float* __restrict__ s0, const float* __restrict__ s1,
                                const float* __restrict__ s2, const float* __restrict__ s3,
                                const float* __restrict__ s4, const float* __restrict__ s5,
                                const float* __restrict__ s6, __half2* __restrict__ dst,
                                const int* __restrict__ l1a, const int* __restrict__ l1b,
                                const int* __restrict__ l2a, const int* __restrict__ l2b,
                                const int* __restrict__ l3a, const int* __restrict__ l3b,
                                int* __restrict__ rec) {
    if (blockIdx.x >= MIX_BLOCKS) {
        int j = (blockIdx.x - MIX_BLOCKS) * 128 + threadIdx.x;
        if (j >= 10240) return;
        int a2 = l3a[j], b2 = l3b[j];
        int a1 = l2a[a2], b1 = l2b[a2], c1 = l2a[b2], d1 = l2b[b2];
        int* r = rec + j * 16;
        r[0] = l1a[a1]; r[1] = l1b[a1];
        r[2] = l1a[b1]; r[3] = l1b[b1];
        r[4] = l1a[c1]; r[5] = l1b[c1];
        r[6] = l1a[d1]; r[7] = l1b[d1];
        r[8]  = OFF_L1 + a1; r[9]  = OFF_L1 + b1;
        r[10] = OFF_L1 + c1; r[11] = OFF_L1 + d1;
        r[12] = OFF_L2 + a2; r[13] = OFF_L2 + b2;
        r[14] = OFF_L3 + j;  r[15] = 0;
        return;
    }
    int tid = blockIdx.x * 128 + threadIdx.x;
    if (tid >= N_NODES) return;
    const int offs[8] = {OFF_C1, OFF_C2, OFF_C3, OFF_C4, OFF_L1, OFF_L2, OFF_L3, N_NODES};
    const float* srcs[7] = {s0, s1, s2, s3, s4, s5, s6};
    int seg = 0;
    while (tid >= offs[seg + 1]) seg++;
    const float* w = srcs[seg] + (size_t)(tid - offs[seg]) * 16;

    float e[16];
    float mx = w[0];
#pragma unroll
    for (int i = 1; i < 16; i++) mx = fmaxf(mx, w[i]);
    float s = 0.f;
#pragma unroll
    for (int i = 0; i < 16; i++) { e[i] = __expf(w[i] - mx); s += e[i]; }
    float inv = 1.f / s;
    float m0 = 0.f, m1 = 0.f, m2 = 0.f, m3 = 0.f;
#pragma unroll
    for (int i = 0; i < 16; i++) {
        float p = e[i] * inv;
        m0 = fmaf(p, GC[i * 4 + 0], m0);
        m1 = fmaf(p, GC[i * 4 + 1], m1);
        m2 = fmaf(p, GC[i * 4 + 2], m2);
        m3 = fmaf(p, GC[i * 4 + 3], m3);
    }
    dst[tid * 4 + 0] = __float2half2_rn(m0);
    dst[tid * 4 + 1] = __float2half2_rn(m1);
    dst[tid * 4 + 2] = __float2half2_rn(m2);
    dst[tid * 4 + 3] = __float2half2_rn(m3);
}

// ---------------- kernel 2: binarize + BCHW -> CHWB fp16 (padded out) ------
__global__ void binarize_kernel(const float* __restrict__ x, __half* __restrict__ bin) {
    __shared__ float tile[32][33];
    int c = blockIdx.z;
    int h = blockIdx.y;
    int bc = blockIdx.x;
    int b = bc * 32 + threadIdx.y;
    tile[threadIdx.y][threadIdx.x] = x[(((size_t)b * 3 + c) * 32 + h) * 32 + threadIdx.x];
    __syncthreads();
    int w = threadIdx.y;
    int bout = bc * 32 + threadIdx.x;
    float v = tile[threadIdx.x][w];
    const float thr[3] = {0.25f, 0.5f, 0.75f};
    const __half one = __float2half(1.f), zero = __float2half(0.f);
#pragma unroll
    for (int t = 0; t < 3; t++) {
        size_t idx = (((size_t)(t * 3 + c)) * 34 * 34 + (size_t)(h + 1) * 34 + (w + 1)) * BB + bout;
        bin[idx] = (v > thr[t]) ? one : zero;
    }
}

// ---------------- tree_conv + or_pool: uint4 lanes, smem coefs -------------
// 16 lanes per (o,s) op. Coefs live in shared memory (consumed per-gate via
// LDS.128) so registers hold only the gather payload -> higher occupancy.
template <int Hin, int SPB, bool PADOUT>
__global__ void __launch_bounds__(SPB * 16, 4) tree_conv4_kernel(
    const uint4* __restrict__ in, uint4* __restrict__ out,
    const int* __restrict__ leaf, const uint4* __restrict__ mix4) {
    constexpr int Win = Hin + 2;
    constexpr int Wo = Hin / 2;
    constexpr int Wop = PADOUT ? (Wo + 2) : Wo;
    constexpr int PSTRIDE = 16;   // uint4 per pixel
    int o = blockIdx.y;

    __shared__ uint4 scf[7];
    __shared__ int ssoff[8];
    int tid = threadIdx.x;
    if (tid < 7) scf[tid] = __ldg(&mix4[o * 7 + tid]);
    if (tid < 8) {
        int idx = __ldg(&leaf[o * 8 + tid]);
        int ch = idx / 9, p = idx % 9;
        ssoff[tid] = (ch * Win * Win + (p / 3) * Win + (p % 3)) * PSTRIDE;
    }
    __syncthreads();

    int lane = tid & 15;
    int s = blockIdx.x * SPB + (tid >> 4);
    int ho = s / Wo, wo = s % Wo;

    int soff[8];
#pragma unroll
    for (int l = 0; l < 8; l++) soff[l] = ssoff[l];

    uint4 r;
    {
        __half2 neg = __float2half2_rn(-60000.f);
        r.x = h2u(neg); r.y = h2u(neg); r.z = h2u(neg); r.w = h2u(neg);
    }
#pragma unroll
    for (int ph = 0; ph < 2; ph++) {
#pragma unroll
        for (int pw = 0; pw < 2; pw++) {
            int pos = ((2 * ho + ph) * Win + (2 * wo + pw)) * PSTRIDE + lane;
            uint4 v[8];
#pragma unroll
            for (int l = 0; l < 8; l++) v[l] = in[soff[l] + pos];
            uint4 ga = gate4u(v[0], v[1], scf[0]);
            uint4 gb = gate4u(v[2], v[3], scf[1]);
            uint4 gc = gate4u(v[4], v[5], scf[2]);
            uint4 gd = gate4u(v[6], v[7], scf[3]);
            uint4 e0 = gate4u(ga, gb, scf[4]);
            uint4 e1 = gate4u(gc, gd, scf[5]);
            uint4 z  = gate4u(e0, e1, scf[6]);
            r = max4u(r, z);
        }
    }
    size_t oidx;
    if (PADOUT)
        oidx = ((size_t)o * Wop * Wop + (size_t)(ho + 1) * Wop + (wo + 1)) * PSTRIDE + lane;
    else
        oidx = ((size_t)o * Wo * Wo + s) * PSTRIDE + lane;
    out[oidx] = r;
}

// ---------------- fused logic1+2+3 + group-sum ------------------------------
__global__ void __launch_bounds__(256) logic_fused_kernel(
    const uint4* __restrict__ h4, const int* __restrict__ rec,
    const uint4* __restrict__ mixh4, float* __restrict__ part) {
    __shared__ float red[16][16][8];
    int lane = threadIdx.x & 15;
    int slot = threadIdx.x >> 4;
    int j = blockIdx.x * 16 + slot;
    const int* r = rec + j * 16;

    uint4 cf[7];
#pragma unroll
    for (int k = 0; k < 7; k++) cf[k] = mixh4[__ldg(&r[8 + k])];
    uint4 v[8];
#pragma unroll
    for (int l = 0; l < 8; l++) v[l] = h4[(size_t)__ldg(&r[l]) * 16 + lane];

    uint4 ga = gate4u(v[0], v[1], cf[0]);
    uint4 gb = gate4u(v[2], v[3], cf[1]);
    uint4 gc = gate4u(v[4], v[5], cf[2]);
    uint4 gd = gate4u(v[6], v[7], cf[3]);
    uint4 e0 = gate4u(ga, gb, cf[4]);
    uint4 e1 = gate4u(gc, gd, cf[5]);
    uint4 z  = gate4u(e0, e1, cf[6]);

    float2 f0 = __half22float2(u2h(z.x));
    float2 f1 = __half22float2(u2h(z.y));
    float2 f2 = __half22float2(u2h(z.z));
    float2 f3 = __half22float2(u2h(z.w));
    red[slot][lane][0] = f0.x; red[slot][lane][1] = f0.y;
    red[slot][lane][2] = f1.x; red[slot][lane][3] = f1.y;
    red[slot][lane][4] = f2.x; red[slot][lane][5] = f2.y;
    red[slot][lane][6] = f3.x; red[slot][lane][7] = f3.y;
    __syncthreads();
    if (threadIdx.x < 128) {
        int ol = threadIdx.x & 15, kk = threadIdx.x >> 4;
        float s = 0.f;
#pragma unroll
        for (int sl = 0; sl < 16; sl++) s += red[sl][ol][kk];
        part[blockIdx.x * BB + ol * 8 + kk] = s;
    }
}

// ---------------- final reduce ----------------
__global__ void final_sum_kernel(const float* __restrict__ part, float* __restrict__ out) {
    int tid = blockIdx.x * blockDim.x + threadIdx.x;
    if (tid >= 1280) return;
    int cls = tid >> 7, b = tid & 127;
    float s = 0.f;
#pragma unroll
    for (int k = 0; k < 64; k++) s += part[(size_t)(cls * 64 + k) * BB + b];
    out[b * 10 + cls] = s * 0.01f;
}

// ---------------- host launcher ----------------
extern "C" void kernel_launch(void* const* d_in, const int* in_sizes, int n_in,
                              void* d_out, int out_size) {
    const float* x   = (const float*)d_in[0];
    const int*   c1i = (const int*)d_in[1];  const float* c1w = (const float*)d_in[2];
    const int*   c2i = (const int*)d_in[3];  const float* c2w = (const float*)d_in[4];
    const int*   c3i = (const int*)d_in[5];  const float* c3w = (const float*)d_in[6];
    const int*   c4i = (const int*)d_in[7];  const float* c4w = (const float*)d_in[8];
    const int*   l1a = (const int*)d_in[9];  const int* l1b = (const int*)d_in[10];
    const float* l1w = (const float*)d_in[11];
    const int*   l2a = (const int*)d_in[12]; const int* l2b = (const int*)d_in[13];
    const float* l2w = (const float*)d_in[14];
    const int*   l3a = (const int*)d_in[15]; const int* l3b = (const int*)d_in[16];
    const float* l3w = (const float*)d_in[17];

    __half *bin, *h1, *h2, *h3, *h4;
    __half2* mixh;
    float* part;
    int* rec;
    cudaGetSymbolAddress((void**)&bin,  g_bin);
    cudaGetSymbolAddress((void**)&h1,   g_h1);
    cudaGetSymbolAddress((void**)&h2,   g_h2);
    cudaGetSymbolAddress((void**)&h3,   g_h3);
    cudaGetSymbolAddress((void**)&h4,   g_h4);
    cudaGetSymbolAddress((void**)&mixh, g_mixh);
    cudaGetSymbolAddress((void**)&part, g_part);
    cudaGetSymbolAddress((void**)&rec,  g_rec);

    const uint4* mix4 = (const uint4*)mixh;

    mix_prep_kernel<<<MIX_BLOCKS + 80, 128>>>(c1w, c2w, c3w, c4w, l1w, l2w, l3w, mixh,
                                              l1a, l1b, l2a, l2b, l3a, l3b, rec);
    binarize_kernel<<<dim3(4, 32, 3), dim3(32, 32)>>>(x, bin);

    tree_conv4_kernel<32, 16, true> <<<dim3(16, 32),  256>>>((const uint4*)bin, (uint4*)h1, c1i, mix4 + OFF_C1);
    tree_conv4_kernel<16, 16, true> <<<dim3(4, 128),  256>>>((const uint4*)h1,  (uint4*)h2, c2i, mix4 + OFF_C2);
    tree_conv4_kernel<8, 16, true>  <<<dim3(1, 512),  256>>>((const uint4*)h2,  (uint4*)h3, c3i, mix4 + OFF_C3);
    tree_conv4_kernel<4, 4, false> <<<dim3(1, 1024),  64>>>((const uint4*)h3,  (uint4*)h4, c4i, mix4 + OFF_C4);

    logic_fused_kernel<<<640, 256>>>((const uint4*)h4, rec, mix4, part);
    final_sum_kernel<<<10, 128>>>(part, (float*)d_out);
}

// round 17
// speedup vs baseline: 1.0520x; 1.0520x over previous
#include <cuda_runtime.h>
#include <cuda_fp16.h>

#define BB 128  // batch
#define BU 32   // batch in uint2 units

// ---------------- padded geometry, fp16 (halos stay zero: never written) ---
__device__ __align__(16) __half g_bin[9 * 34 * 34 * BB];
__device__ __align__(16) __half g_h1[32 * 18 * 18 * BB];
__device__ __align__(16) __half g_h2[128 * 10 * 10 * BB];
__device__ __align__(16) __half g_h3[512 * 6 * 6 * BB];
__device__ __align__(16) __half g_h4[4096 * BB];
__device__ __align__(16) __half2 g_mixh[83552 * 4];
__device__ __align__(16) int g_rec[10240 * 16];
__device__ __align__(16) float g_part[640 * BB];

__constant__ float GC[64] = {
    0, 0, 0, 0,   0, 0, 0, 1,   0, 1, 0, -1,  0, 1, 0, 0,
    0, 0, 1, -1,  0, 0, 1, 0,   0, 1, 1, -2,  0, 1, 1, -1,
    1, -1, -1, 1, 1, -1, -1, 2, 1, 0, -1, 0,  1, 0, -1, 1,
    1, -1, 0, 0,  1, -1, 0, 1,  1, 0, 0, -1,  1, 0, 0, 0};

#define OFF_C1 0
#define OFF_C2 224
#define OFF_C3 1120
#define OFF_C4 4704
#define OFF_L1 11872
#define OFF_L2 52832
#define OFF_L3 73312
#define N_NODES 83552
#define MIX_BLOCKS 653   // ceil(83552/128)

// ---------------- helpers ----------------
__device__ __forceinline__ __half2 u2h(unsigned int u) {
    __half2 h;
    *reinterpret_cast<unsigned int*>(&h) = u;
    return h;
}
__device__ __forceinline__ unsigned int h2u(__half2 h) {
    return *reinterpret_cast<unsigned int*>(&h);
}
__device__ __forceinline__ __half2 gateh(__half2 a, __half2 b,
                                         __half2 w0, __half2 w1, __half2 w2, __half2 w3) {
    return __hfma2(__hmul2(a, b), w3, __hfma2(b, w2, __hfma2(a, w1, w0)));
}
__device__ __forceinline__ uint4 gate4u(uint4 a, uint4 b, uint4 cf) {
    __half2 w0 = u2h(cf.x), w1 = u2h(cf.y), w2 = u2h(cf.z), w3 = u2h(cf.w);
    uint4 r;
    r.x = h2u(gateh(u2h(a.x), u2h(b.x), w0, w1, w2, w3));
    r.y = h2u(gateh(u2h(a.y), u2h(b.y), w0, w1, w2, w3));
    r.z = h2u(gateh(u2h(a.z), u2h(b.z), w0, w1, w2, w3));
    r.w = h2u(gateh(u2h(a.w), u2h(b.w), w0, w1, w2, w3));
    return r;
}
__device__ __forceinline__ uint4 max4u(uint4 a, uint4 b) {
    uint4 r;
    r.x = h2u(__hmax2(u2h(a.x), u2h(b.x)));
    r.y = h2u(__hmax2(u2h(a.y), u2h(b.y)));
    r.z = h2u(__hmax2(u2h(a.z), u2h(b.z)));
    r.w = h2u(__hmax2(u2h(a.w), u2h(b.w)));
    return r;
}

// ---------------- kernel 1: gate mixing + logic-chain prep (merged) --------
__global__ void mix_prep_kernel(const float* __restrict__ s0, const float* __restrict__ s1,
                                const float* __restrict__ s2, const float* __restrict__ s3,
                                const float* __restrict__ s4, const float* __restrict__ s5,
                                const float* __restrict__ s6, __half2* __restrict__ dst,
                                const int* __restrict__ l1a, const int* __restrict__ l1b,
                                const int* __restrict__ l2a, const int* __restrict__ l2b,
                                const int* __restrict__ l3a, const int* __restrict__ l3b,
                                int* __restrict__ rec) {
    if (blockIdx.x >= MIX_BLOCKS) {
        int j = (blockIdx.x - MIX_BLOCKS) * 128 + threadIdx.x;
        if (j >= 10240) return;
        int a2 = l3a[j], b2 = l3b[j];
        int a1 = l2a[a2], b1 = l2b[a2], c1 = l2a[b2], d1 = l2b[b2];
        int* r = rec + j * 16;
        r[0] = l1a[a1]; r[1] = l1b[a1];
        r[2] = l1a[b1]; r[3] = l1b[b1];
        r[4] = l1a[c1]; r[5] = l1b[c1];
        r[6] = l1a[d1]; r[7] = l1b[d1];
        r[8]  = OFF_L1 + a1; r[9]  = OFF_L1 + b1;
        r[10] = OFF_L1 + c1; r[11] = OFF_L1 + d1;
        r[12] = OFF_L2 + a2; r[13] = OFF_L2 + b2;
        r[14] = OFF_L3 + j;  r[15] = 0;
        return;
    }
    int tid = blockIdx.x * 128 + threadIdx.x;
    if (tid >= N_NODES) return;
    const int offs[8] = {OFF_C1, OFF_C2, OFF_C3, OFF_C4, OFF_L1, OFF_L2, OFF_L3, N_NODES};
    const float* srcs[7] = {s0, s1, s2, s3, s4, s5, s6};
    int seg = 0;
    while (tid >= offs[seg + 1]) seg++;
    const float* w = srcs[seg] + (size_t)(tid - offs[seg]) * 16;

    float e[16];
    float mx = w[0];
#pragma unroll
    for (int i = 1; i < 16; i++) mx = fmaxf(mx, w[i]);
    float s = 0.f;
#pragma unroll
    for (int i = 0; i < 16; i++) { e[i] = __expf(w[i] - mx); s += e[i]; }
    float inv = 1.f / s;
    float m0 = 0.f, m1 = 0.f, m2 = 0.f, m3 = 0.f;
#pragma unroll
    for (int i = 0; i < 16; i++) {
        float p = e[i] * inv;
        m0 = fmaf(p, GC[i * 4 + 0], m0);
        m1 = fmaf(p, GC[i * 4 + 1], m1);
        m2 = fmaf(p, GC[i * 4 + 2], m2);
        m3 = fmaf(p, GC[i * 4 + 3], m3);
    }
    dst[tid * 4 + 0] = __float2half2_rn(m0);
    dst[tid * 4 + 1] = __float2half2_rn(m1);
    dst[tid * 4 + 2] = __float2half2_rn(m2);
    dst[tid * 4 + 3] = __float2half2_rn(m3);
}

// ---------------- kernel 2: binarize + BCHW -> CHWB fp16 (padded out) ------
__global__ void binarize_kernel(const float* __restrict__ x, __half* __restrict__ bin) {
    __shared__ float tile[32][33];
    int c = blockIdx.z;
    int h = blockIdx.y;
    int bc = blockIdx.x;
    int b = bc * 32 + threadIdx.y;
    tile[threadIdx.y][threadIdx.x] = x[(((size_t)b * 3 + c) * 32 + h) * 32 + threadIdx.x];
    __syncthreads();
    int w = threadIdx.y;
    int bout = bc * 32 + threadIdx.x;
    float v = tile[threadIdx.x][w];
    const float thr[3] = {0.25f, 0.5f, 0.75f};
    const __half one = __float2half(1.f), zero = __float2half(0.f);
#pragma unroll
    for (int t = 0; t < 3; t++) {
        size_t idx = (((size_t)(t * 3 + c)) * 34 * 34 + (size_t)(h + 1) * 34 + (w + 1)) * BB + bout;
        bin[idx] = (v > thr[t]) ? one : zero;
    }
}

// ---------------- tree_conv + or_pool: uint4 lanes, register coefs ---------
// 16 lanes per (o,s) op. min-blocks=3 caps regs ~84 -> 29% occupancy.
template <int Hin, int SPB, bool PADOUT>
__global__ void __launch_bounds__(SPB * 16, 3) tree_conv4_kernel(
    const uint4* __restrict__ in, uint4* __restrict__ out,
    const int* __restrict__ leaf, const uint4* __restrict__ mix4) {
    constexpr int Win = Hin + 2;
    constexpr int Wo = Hin / 2;
    constexpr int Wop = PADOUT ? (Wo + 2) : Wo;
    constexpr int PSTRIDE = 16;   // uint4 per pixel
    int o = blockIdx.y;

    // broadcast loads: coefs (uint4 per gate) and leaf offsets
    uint4 cf[7];
#pragma unroll
    for (int g = 0; g < 7; g++) cf[g] = __ldg(&mix4[o * 7 + g]);
    int soff[8];
#pragma unroll
    for (int l = 0; l < 8; l++) {
        int idx = __ldg(&leaf[o * 8 + l]);
        int ch = idx / 9, p = idx % 9;
        soff[l] = (ch * Win * Win + (p / 3) * Win + (p % 3)) * PSTRIDE;
    }

    int tid = threadIdx.x;
    int lane = tid & 15;          // uint4 lane over batch
    int s = blockIdx.x * SPB + (tid >> 4);
    int ho = s / Wo, wo = s % Wo;

    uint4 r;
    {
        __half2 neg = __float2half2_rn(-60000.f);
        r.x = h2u(neg); r.y = h2u(neg); r.z = h2u(neg); r.w = h2u(neg);
    }
#pragma unroll
    for (int ph = 0; ph < 2; ph++) {
#pragma unroll
        for (int pw = 0; pw < 2; pw++) {
            int pos = ((2 * ho + ph) * Win + (2 * wo + pw)) * PSTRIDE + lane;
            uint4 v[8];
#pragma unroll
            for (int l = 0; l < 8; l++) v[l] = in[soff[l] + pos];
            uint4 ga = gate4u(v[0], v[1], cf[0]);
            uint4 gb = gate4u(v[2], v[3], cf[1]);
            uint4 gc = gate4u(v[4], v[5], cf[2]);
            uint4 gd = gate4u(v[6], v[7], cf[3]);
            uint4 e0 = gate4u(ga, gb, cf[4]);
            uint4 e1 = gate4u(gc, gd, cf[5]);
            uint4 z  = gate4u(e0, e1, cf[6]);
            r = max4u(r, z);
        }
    }
    size_t oidx;
    if (PADOUT)
        oidx = ((size_t)o * Wop * Wop + (size_t)(ho + 1) * Wop + (wo + 1)) * PSTRIDE + lane;
    else
        oidx = ((size_t)o * Wo * Wo + s) * PSTRIDE + lane;
    out[oidx] = r;
}

// ---------------- fused logic1+2+3 + group-sum ------------------------------
__global__ void __launch_bounds__(256) logic_fused_kernel(
    const uint4* __restrict__ h4, const int* __restrict__ rec,
    const uint4* __restrict__ mixh4, float* __restrict__ part) {
    __shared__ float red[16][16][8];
    int lane = threadIdx.x & 15;
    int slot = threadIdx.x >> 4;
    int j = blockIdx.x * 16 + slot;
    const int* r = rec + j * 16;

    uint4 cf[7];
#pragma unroll
    for (int k = 0; k < 7; k++) cf[k] = mixh4[__ldg(&r[8 + k])];
    uint4 v[8];
#pragma unroll
    for (int l = 0; l < 8; l++) v[l] = h4[(size_t)__ldg(&r[l]) * 16 + lane];

    uint4 ga = gate4u(v[0], v[1], cf[0]);
    uint4 gb = gate4u(v[2], v[3], cf[1]);
    uint4 gc = gate4u(v[4], v[5], cf[2]);
    uint4 gd = gate4u(v[6], v[7], cf[3]);
    uint4 e0 = gate4u(ga, gb, cf[4]);
    uint4 e1 = gate4u(gc, gd, cf[5]);
    uint4 z  = gate4u(e0, e1, cf[6]);

    float2 f0 = __half22float2(u2h(z.x));
    float2 f1 = __half22float2(u2h(z.y));
    float2 f2 = __half22float2(u2h(z.z));
    float2 f3 = __half22float2(u2h(z.w));
    red[slot][lane][0] = f0.x; red[slot][lane][1] = f0.y;
    red[slot][lane][2] = f1.x; red[slot][lane][3] = f1.y;
    red[slot][lane][4] = f2.x; red[slot][lane][5] = f2.y;
    red[slot][lane][6] = f3.x; red[slot][lane][7] = f3.y;
    __syncthreads();
    if (threadIdx.x < 128) {
        int ol = threadIdx.x & 15, kk = threadIdx.x >> 4;
        float s = 0.f;
#pragma unroll
        for (int sl = 0; sl < 16; sl++) s += red[sl][ol][kk];
        part[blockIdx.x * BB + ol * 8 + kk] = s;
    }
}

// ---------------- final reduce ----------------
__global__ void final_sum_kernel(const float* __restrict__ part, float* __restrict__ out) {
    int tid = blockIdx.x * blockDim.x + threadIdx.x;
    if (tid >= 1280) return;
    int cls = tid >> 7, b = tid & 127;
    float s = 0.f;
#pragma unroll
    for (int k = 0; k < 64; k++) s += part[(size_t)(cls * 64 + k) * BB + b];
    out[b * 10 + cls] = s * 0.01f;
}

// ---------------- host launcher ----------------
extern "C" void kernel_launch(void* const* d_in, const int* in_sizes, int n_in,
                              void* d_out, int out_size) {
    const float* x   = (const float*)d_in[0];
    const int*   c1i = (const int*)d_in[1];  const float* c1w = (const float*)d_in[2];
    const int*   c2i = (const int*)d_in[3];  const float* c2w = (const float*)d_in[4];
    const int*   c3i = (const int*)d_in[5];  const float* c3w = (const float*)d_in[6];
    const int*   c4i = (const int*)d_in[7];  const float* c4w = (const float*)d_in[8];
    const int*   l1a = (const int*)d_in[9];  const int* l1b = (const int*)d_in[10];
    const float* l1w = (const float*)d_in[11];
    const int*   l2a = (const int*)d_in[12]; const int* l2b = (const int*)d_in[13];
    const float* l2w = (const float*)d_in[14];
    const int*   l3a = (const int*)d_in[15]; const int* l3b = (const int*)d_in[16];
    const float* l3w = (const float*)d_in[17];

    __half *bin, *h1, *h2, *h3, *h4;
    __half2* mixh;
    float* part;
    int* rec;
    cudaGetSymbolAddress((void**)&bin,  g_bin);
    cudaGetSymbolAddress((void**)&h1,   g_h1);
    cudaGetSymbolAddress((void**)&h2,   g_h2);
    cudaGetSymbolAddress((void**)&h3,   g_h3);
    cudaGetSymbolAddress((void**)&h4,   g_h4);
    cudaGetSymbolAddress((void**)&mixh, g_mixh);
    cudaGetSymbolAddress((void**)&part, g_part);
    cudaGetSymbolAddress((void**)&rec,  g_rec);

    const uint4* mix4 = (const uint4*)mixh;

    mix_prep_kernel<<<MIX_BLOCKS + 80, 128>>>(c1w, c2w, c3w, c4w, l1w, l2w, l3w, mixh,
                                              l1a, l1b, l2a, l2b, l3a, l3b, rec);
    binarize_kernel<<<dim3(4, 32, 3), dim3(32, 32)>>>(x, bin);

    tree_conv4_kernel<32, 16, true> <<<dim3(16, 32),  256>>>((const uint4*)bin, (uint4*)h1, c1i, mix4 + OFF_C1);
    tree_conv4_kernel<16, 16, true> <<<dim3(4, 128),  256>>>((const uint4*)h1,  (uint4*)h2, c2i, mix4 + OFF_C2);
    tree_conv4_kernel<8, 16, true>  <<<dim3(1, 512),  256>>>((const uint4*)h2,  (uint4*)h3, c3i, mix4 + OFF_C3);
    tree_conv4_kernel<4, 4, false> <<<dim3(1, 1024),  64>>>((const uint4*)h3,  (uint4*)h4, c4i, mix4 + OFF_C4);

    logic_fused_kernel<<<640, 256>>>((const uint4*)h4, rec, mix4, part);
    final_sum_kernel<<<10, 128>>>(part, (float*)d_out);
}